// round 1
// baseline (speedup 1.0000x reference)
#include <cuda_runtime.h>
#include <math.h>

// Problem constants (fixed shapes from reference)
#define T_TOK 8192      // B*S
#define D_DIM 1024
#define H_DIM 4096
#define E_NUM 8
#define TOPK  2

// ---------------------------------------------------------------------------
// Scratch (static __device__ — no allocations allowed)
// ---------------------------------------------------------------------------
__device__ int   g_cnt[E_NUM];
__device__ int   g_off[E_NUM];
__device__ int   g_perm[E_NUM * T_TOK];   // token id per (expert, slot)
__device__ float g_wt  [E_NUM * T_TOK];   // combine weight per (expert, slot)
// Hidden activations for all routed (token,expert) pairs: 16384 x 4096 fp32 = 256 MB
__device__ float g_hidden[T_TOK * TOPK * H_DIM];

// ---------------------------------------------------------------------------
// K0: zero output + reset per-expert counters
// ---------------------------------------------------------------------------
__global__ void k_init(float* __restrict__ out, int n) {
    if (blockIdx.x == 0 && threadIdx.x < E_NUM) g_cnt[threadIdx.x] = 0;
    int i = blockIdx.x * blockDim.x + threadIdx.x;
    int stride = gridDim.x * blockDim.x;
    for (; i < n; i += stride) out[i] = 0.0f;
}

// ---------------------------------------------------------------------------
// K1: gating — one warp per token. gates = x @ gate_w + gate_b; top-2; softmax;
// compact into per-expert lists via atomics.
// ---------------------------------------------------------------------------
__global__ void k_gate(const float* __restrict__ x,
                       const float* __restrict__ gw,
                       const float* __restrict__ gb) {
    int warp = (blockIdx.x * blockDim.x + threadIdx.x) >> 5;
    int lane = threadIdx.x & 31;
    if (warp >= T_TOK) return;
    const float* xr = x + (size_t)warp * D_DIM;

    float acc[E_NUM];
#pragma unroll
    for (int e = 0; e < E_NUM; e++) acc[e] = 0.0f;

    for (int d = lane; d < D_DIM; d += 32) {
        float xv = xr[d];
        const float* g = gw + d * E_NUM;
#pragma unroll
        for (int e = 0; e < E_NUM; e++) acc[e] += xv * g[e];
    }
#pragma unroll
    for (int e = 0; e < E_NUM; e++) {
#pragma unroll
        for (int o = 16; o > 0; o >>= 1)
            acc[e] += __shfl_xor_sync(0xFFFFFFFFu, acc[e], o);
    }

    if (lane == 0) {
        float best = -1e30f, sec = -1e30f;
        int bi = 0, si = 0;
#pragma unroll
        for (int e = 0; e < E_NUM; e++) {
            float v = acc[e] + gb[e];
            if (v > best) { sec = best; si = bi; best = v; bi = e; }
            else if (v > sec) { sec = v; si = e; }
        }
        // softmax over the two selected scores
        float g1 = 1.0f / (1.0f + expf(best - sec));  // weight of 2nd
        float g0 = 1.0f - g1;                          // weight of best
        int p0 = atomicAdd(&g_cnt[bi], 1);
        g_perm[bi * T_TOK + p0] = warp;
        g_wt  [bi * T_TOK + p0] = g0;
        int p1 = atomicAdd(&g_cnt[si], 1);
        g_perm[si * T_TOK + p1] = warp;
        g_wt  [si * T_TOK + p1] = g1;
    }
}

// ---------------------------------------------------------------------------
// K2: prefix-sum expert offsets (E=8, trivial)
// ---------------------------------------------------------------------------
__global__ void k_off() {
    if (threadIdx.x == 0 && blockIdx.x == 0) {
        int s = 0;
#pragma unroll
        for (int e = 0; e < E_NUM; e++) { g_off[e] = s; s += g_cnt[e]; }
    }
}

// ---------------------------------------------------------------------------
// Grouped SGEMM core: BM=BN=128, BK=8, 256 threads, 8x8 microtile.
// ---------------------------------------------------------------------------

// K3: hidden[off_e + m, :] = gelu( x[perm_e[m], :] @ w1[e] + b1[e] )
__global__ __launch_bounds__(256)
void k_gemm1(const float* __restrict__ x,
             const float* __restrict__ w1,
             const float* __restrict__ b1) {
    int e   = blockIdx.z;
    int cnt = g_cnt[e];
    int m0  = blockIdx.y * 128;
    if (m0 >= cnt) return;
    int n0  = blockIdx.x * 128;

    __shared__ float As[8][128];
    __shared__ float Bs[8][128];

    int tid = threadIdx.x;
    // A-load mapping: one float4 per thread: m = tid/2, k-offset = (tid&1)*4
    int am = tid >> 1;
    int ak = (tid & 1) * 4;
    int tok = -1;
    if (m0 + am < cnt) tok = g_perm[e * T_TOK + m0 + am];
    // B-load mapping: kr = tid/32, n-offset = (tid&31)*4
    int bk = tid >> 5;
    int bn = (tid & 31) * 4;
    const float* w1e = w1 + (size_t)e * D_DIM * H_DIM;

    int tx = tid & 15, ty = tid >> 4;
    float acc[8][8];
#pragma unroll
    for (int i = 0; i < 8; i++)
#pragma unroll
        for (int j = 0; j < 8; j++) acc[i][j] = 0.0f;

    for (int k0 = 0; k0 < D_DIM; k0 += 8) {
        float4 av = make_float4(0.f, 0.f, 0.f, 0.f);
        if (tok >= 0) av = *(const float4*)(x + (size_t)tok * D_DIM + k0 + ak);
        float4 bv = *(const float4*)(w1e + (size_t)(k0 + bk) * H_DIM + n0 + bn);
        __syncthreads();
        As[ak + 0][am] = av.x; As[ak + 1][am] = av.y;
        As[ak + 2][am] = av.z; As[ak + 3][am] = av.w;
        *(float4*)&Bs[bk][bn] = bv;
        __syncthreads();
#pragma unroll
        for (int k = 0; k < 8; k++) {
            float a[8], b[8];
            *(float4*)(a)     = *(float4*)&As[k][ty * 4];
            *(float4*)(a + 4) = *(float4*)&As[k][64 + ty * 4];
            *(float4*)(b)     = *(float4*)&Bs[k][tx * 4];
            *(float4*)(b + 4) = *(float4*)&Bs[k][64 + tx * 4];
#pragma unroll
            for (int i = 0; i < 8; i++)
#pragma unroll
                for (int j = 0; j < 8; j++) acc[i][j] += a[i] * b[j];
        }
    }

    int off = g_off[e];
    const float* b1e = b1 + e * H_DIM;
#pragma unroll
    for (int i = 0; i < 8; i++) {
        int rm = (i < 4) ? (ty * 4 + i) : (64 + ty * 4 + (i - 4));
        int m = m0 + rm;
        if (m >= cnt) continue;
        float* hrow = g_hidden + (size_t)(off + m) * H_DIM;
#pragma unroll
        for (int j = 0; j < 8; j++) {
            int rn = (j < 4) ? (tx * 4 + j) : (64 + tx * 4 + (j - 4));
            int n = n0 + rn;
            float h = acc[i][j] + b1e[n];
            // exact GELU: 0.5*h*(1+erf(h/sqrt(2)))
            h = 0.5f * h * (1.0f + erff(h * 0.70710678118654752f));
            hrow[n] = h;
        }
    }
}

// K4: out[tok, :] += wt * ( hidden[off_e + m, :] @ w2[e] + b2[e] )
__global__ __launch_bounds__(256)
void k_gemm2(const float* __restrict__ w2,
             const float* __restrict__ b2,
             float* __restrict__ out) {
    int e   = blockIdx.z;
    int cnt = g_cnt[e];
    int m0  = blockIdx.y * 128;
    if (m0 >= cnt) return;
    int n0  = blockIdx.x * 128;
    int off = g_off[e];

    __shared__ float As[8][128];
    __shared__ float Bs[8][128];

    int tid = threadIdx.x;
    int am = tid >> 1;
    int ak = (tid & 1) * 4;
    bool avalid = (m0 + am < cnt);
    const float* arow = g_hidden + (size_t)(off + m0 + am) * H_DIM;
    int bk = tid >> 5;
    int bn = (tid & 31) * 4;
    const float* w2e = w2 + (size_t)e * H_DIM * D_DIM;

    int tx = tid & 15, ty = tid >> 4;
    float acc[8][8];
#pragma unroll
    for (int i = 0; i < 8; i++)
#pragma unroll
        for (int j = 0; j < 8; j++) acc[i][j] = 0.0f;

    for (int k0 = 0; k0 < H_DIM; k0 += 8) {
        float4 av = make_float4(0.f, 0.f, 0.f, 0.f);
        if (avalid) av = *(const float4*)(arow + k0 + ak);
        float4 bv = *(const float4*)(w2e + (size_t)(k0 + bk) * D_DIM + n0 + bn);
        __syncthreads();
        As[ak + 0][am] = av.x; As[ak + 1][am] = av.y;
        As[ak + 2][am] = av.z; As[ak + 3][am] = av.w;
        *(float4*)&Bs[bk][bn] = bv;
        __syncthreads();
#pragma unroll
        for (int k = 0; k < 8; k++) {
            float a[8], b[8];
            *(float4*)(a)     = *(float4*)&As[k][ty * 4];
            *(float4*)(a + 4) = *(float4*)&As[k][64 + ty * 4];
            *(float4*)(b)     = *(float4*)&Bs[k][tx * 4];
            *(float4*)(b + 4) = *(float4*)&Bs[k][64 + tx * 4];
#pragma unroll
            for (int i = 0; i < 8; i++)
#pragma unroll
                for (int j = 0; j < 8; j++) acc[i][j] += a[i] * b[j];
        }
    }

    const float* b2e = b2 + e * D_DIM;
#pragma unroll
    for (int i = 0; i < 8; i++) {
        int rm = (i < 4) ? (ty * 4 + i) : (64 + ty * 4 + (i - 4));
        int m = m0 + rm;
        if (m >= cnt) continue;
        int   tok = g_perm[e * T_TOK + m];
        float w   = g_wt  [e * T_TOK + m];
        float* orow = out + (size_t)tok * D_DIM;
#pragma unroll
        for (int j = 0; j < 8; j++) {
            int rn = (j < 4) ? (tx * 4 + j) : (64 + tx * 4 + (j - 4));
            int n = n0 + rn;
            float y = acc[i][j] + b2e[n];
            atomicAdd(&orow[n], w * y);
        }
    }
}

// ---------------------------------------------------------------------------
// Launch
// ---------------------------------------------------------------------------
extern "C" void kernel_launch(void* const* d_in, const int* in_sizes, int n_in,
                              void* d_out, int out_size) {
    const float* x  = (const float*)d_in[0];
    const float* gw = (const float*)d_in[1];
    const float* gb = (const float*)d_in[2];
    const float* w1 = (const float*)d_in[3];
    const float* b1 = (const float*)d_in[4];
    const float* w2 = (const float*)d_in[5];
    const float* b2 = (const float*)d_in[6];
    float* out = (float*)d_out;

    (void)in_sizes; (void)n_in;

    // K0: zero out + reset counters
    k_init<<<2048, 256>>>(out, out_size);
    // K1: gating (8192 warps)
    k_gate<<<(T_TOK * 32 + 255) / 256, 256>>>(x, gw, gb);
    // K2: offsets
    k_off<<<1, 32>>>();
    // K3: grouped GEMM1 + GELU  (H tiles=32, max M tiles=64, E=8)
    k_gemm1<<<dim3(H_DIM / 128, T_TOK / 128, E_NUM), 256>>>(x, w1, b1);
    // K4: grouped GEMM2 + weighted scatter (D tiles=8, max M tiles=64, E=8)
    k_gemm2<<<dim3(D_DIM / 128, T_TOK / 128, E_NUM), 256>>>(w2, b2, out);
}